// round 9
// baseline (speedup 1.0000x reference)
#include <cuda_runtime.h>
#include <cstdint>

#define B_  8
#define N_  512
#define F_  32
#define BN_ (B_ * N_)

#define STAGE_J     64                       // j's per pipeline stage
#define STAGE_BYTES (STAGE_J * F_ * 4)       // 8192 B
#define NBUF        4                        // SMEM ring buffers
#define NSTAGES     (N_ / STAGE_J)           // 8 stages per row
#define DEPTH       2                        // fills in flight (proven-safe)

// Scratch (allocation-free rule: __device__ globals)
__device__ float g_x1[BN_ * F_];

__device__ __forceinline__ uint32_t smem_u32(const void* p) {
    return (uint32_t)__cvta_generic_to_shared(p);
}

// ---------------------------------------------------------------------------
// Prep kernel (x1 only): one warp per (b,n) row, reads x + n_func weights.
//  - g_x1 = relu(relu(x@Wn1+bn1)@Wn2+bn2)
// Self path + A row-sum live in agg now.
// ---------------------------------------------------------------------------
__global__ __launch_bounds__(256)
void prep_kernel(const float* __restrict__ x,
                 const float* __restrict__ Wn1, const float* __restrict__ bn1,
                 const float* __restrict__ Wn2, const float* __restrict__ bn2) {
    const unsigned FULL = 0xffffffffu;
    int row = blockIdx.x * (blockDim.x >> 5) + (threadIdx.x >> 5);
    int f   = threadIdx.x & 31;
    if (row >= BN_) return;

    float xv = x[row * F_ + f];

    float h = bn1[f];
    #pragma unroll
    for (int k = 0; k < F_; k++)
        h = fmaf(__shfl_sync(FULL, xv, k), Wn1[k * F_ + f], h);
    h = fmaxf(h, 0.0f);
    float o1 = bn2[f];
    #pragma unroll
    for (int k = 0; k < F_; k++)
        o1 = fmaf(__shfl_sync(FULL, h, k), Wn2[k * F_ + f], o1);
    g_x1[row * F_ + f] = fmaxf(o1, 0.0f);
}

// ---------------------------------------------------------------------------
// Aggregation + W copy via bulk-async pipeline. One block = one row (bi).
// Proven-safe R6 ordering: consumer wait -> compute -> __syncthreads ->
// copy-out + refill (depth 2, wait_group.read 2).
//  inv:  A row-sum accumulated inline on fq==0 lanes (A read exactly once)
//  xs:   self-path MLP computed in epilogue by warp 0 (own row only)
//  x2:   single plain store (no RMW, no atomics)
// ---------------------------------------------------------------------------
__global__ __launch_bounds__(256)
void agg_kernel(const float* __restrict__ A, const float* __restrict__ W,
                const float* __restrict__ x,
                const float* __restrict__ Ws1, const float* __restrict__ bs1,
                const float* __restrict__ Ws2, const float* __restrict__ bs2,
                float* __restrict__ outW, float* __restrict__ outX2) {
    __shared__ __align__(128) float sbuf[NBUF][STAGE_J * F_];   // 32 KB
    __shared__ __align__(8) unsigned long long mbar[NBUF];
    __shared__ float sacc[8][F_];
    __shared__ float s_asum[8];

    const unsigned FULL = 0xffffffffu;
    int bi   = blockIdx.x;            // row (b*N + i)
    int b    = bi >> 9;               // N_ = 512
    int tid  = threadIdx.x;
    int warp = tid >> 5;
    int lane = tid & 31;
    int fq   = lane & 7;
    int jo   = lane >> 3;

    const char* Wrow = (const char*)(W    + (size_t)bi * N_ * F_);
    char*       Orow = (char*)      (outW + (size_t)bi * N_ * F_);
    const float4* x1p  = (const float4*)(g_x1 + (size_t)b * N_ * F_);
    const float*  Arow = A + (size_t)bi * N_;

    uint32_t sbuf_s = smem_u32(&sbuf[0][0]);
    uint32_t mbar_s = smem_u32(&mbar[0]);

    if (tid == 0) {
        #pragma unroll
        for (int i = 0; i < NBUF; i++)
            asm volatile("mbarrier.init.shared::cta.b64 [%0], 1;"
                         :: "r"(mbar_s + i * 8) : "memory");
    }
    __syncthreads();

    // prologue: fill stages 0..DEPTH-1
    if (tid == 0) {
        #pragma unroll
        for (int s = 0; s < DEPTH; s++) {
            uint32_t mb = mbar_s + s * 8;
            asm volatile("mbarrier.arrive.expect_tx.shared::cta.b64 _, [%0], %1;"
                         :: "r"(mb), "r"((uint32_t)STAGE_BYTES) : "memory");
            asm volatile(
                "cp.async.bulk.shared::cluster.global.mbarrier::complete_tx::bytes"
                " [%0], [%1], %2, [%3];"
                :: "r"(sbuf_s + s * STAGE_BYTES),
                   "l"(Wrow + (size_t)s * STAGE_BYTES),
                   "r"((uint32_t)STAGE_BYTES), "r"(mb) : "memory");
        }
    }

    float4 acc  = make_float4(0.0f, 0.0f, 0.0f, 0.0f);
    float  asum = 0.0f;

    for (int s = 0; s < NSTAGES; s++) {
        int p = s & (NBUF - 1);
        uint32_t mb  = mbar_s + p * 8;
        uint32_t phs = (uint32_t)((s >> 2) & 1);

        // consumer wait (acquire) -- fill for stage s complete
        {
            uint32_t done;
            asm volatile(
                "{ .reg .pred q;\n\t"
                "mbarrier.try_wait.parity.acquire.cta.shared::cta.b64 q, [%1], %2;\n\t"
                "selp.b32 %0, 1, 0, q; }"
                : "=r"(done) : "r"(mb), "r"(phs) : "memory");
            if (!done) {
                asm volatile(
                    "{ .reg .pred q;\n\t"
                    "WL_%=:\n\t"
                    "mbarrier.try_wait.parity.acquire.cta.shared::cta.b64 q, [%0], %1, 0x989680;\n\t"
                    "@q bra.uni WD_%=;\n\t"
                    "bra.uni WL_%=;\n\t"
                    "WD_%=: }"
                    :: "r"(mb), "r"(phs) : "memory");
            }
        }

        uint32_t buf = sbuf_s + p * STAGE_BYTES;

        // compute: warp handles 8 j's of this 64-j stage (2 iters of 4 j)
        #pragma unroll
        for (int k = 0; k < 2; k++) {
            uint32_t a0_, a1_, a2_, a3_;
            asm volatile("ld.shared.v4.b32 {%0,%1,%2,%3}, [%4];"
                         : "=r"(a0_), "=r"(a1_), "=r"(a2_), "=r"(a3_)
                         : "r"(buf + warp * 1024 + k * 512 + lane * 16));
            float4 w4;
            w4.x = __uint_as_float(a0_); w4.y = __uint_as_float(a1_);
            w4.z = __uint_as_float(a2_); w4.w = __uint_as_float(a3_);
            int j = s * STAGE_J + warp * 8 + k * 4 + jo;
            float  a  = __ldg(Arow + j);
            if (fq == 0) asum += a;               // A row-sum (each j once)
            float4 xv = x1p[j * 8 + fq];
            acc.x = fmaf(a * w4.x, xv.x, acc.x);
            acc.y = fmaf(a * w4.y, xv.y, acc.y);
            acc.z = fmaf(a * w4.z, xv.z, acc.z);
            acc.w = fmaf(a * w4.w, xv.w, acc.w);
        }

        __syncthreads();   // all warps done reading buf p

        if (tid == 0) {
            // copy-out this stage (reads SMEM asynchronously)
            asm volatile("cp.async.bulk.global.shared::cta.bulk_group [%0], [%1], %2;"
                         :: "l"(Orow + (size_t)s * STAGE_BYTES),
                            "r"(buf), "r"((uint32_t)STAGE_BYTES) : "memory");
            asm volatile("cp.async.bulk.commit_group;" ::: "memory");

            int s2 = s + DEPTH;
            if (s2 < NSTAGES) {
                // buffer for s2 was copied out at stage s-2; drain its reads
                asm volatile("cp.async.bulk.wait_group.read 2;" ::: "memory");
                int p2 = s2 & (NBUF - 1);
                uint32_t mb2 = mbar_s + p2 * 8;
                asm volatile("mbarrier.arrive.expect_tx.shared::cta.b64 _, [%0], %1;"
                             :: "r"(mb2), "r"((uint32_t)STAGE_BYTES) : "memory");
                asm volatile(
                    "cp.async.bulk.shared::cluster.global.mbarrier::complete_tx::bytes"
                    " [%0], [%1], %2, [%3];"
                    :: "r"(sbuf_s + p2 * STAGE_BYTES),
                       "l"(Wrow + (size_t)s2 * STAGE_BYTES),
                       "r"((uint32_t)STAGE_BYTES), "r"(mb2) : "memory");
            }
        }
    }

    // reduce across the 4 lanes sharing a feature-quad (xor 8, 16)
    #pragma unroll
    for (int o = 8; o <= 16; o <<= 1) {
        acc.x += __shfl_xor_sync(FULL, acc.x, o);
        acc.y += __shfl_xor_sync(FULL, acc.y, o);
        acc.z += __shfl_xor_sync(FULL, acc.z, o);
        acc.w += __shfl_xor_sync(FULL, acc.w, o);
        asum  += __shfl_xor_sync(FULL, asum,  o);
    }
    if (lane < 8) {
        sacc[warp][lane * 4 + 0] = acc.x;
        sacc[warp][lane * 4 + 1] = acc.y;
        sacc[warp][lane * 4 + 2] = acc.z;
        sacc[warp][lane * 4 + 3] = acc.w;
    }
    if (lane == 0) s_asum[warp] = asum;
    __syncthreads();

    // Epilogue (warp 0): self-path MLP for this row + final x2 store.
    if (warp == 0) {
        int f = lane;
        float xv = __ldg(x + (size_t)bi * F_ + f);

        float hs = __ldg(bs1 + f);
        #pragma unroll
        for (int k = 0; k < F_; k++)
            hs = fmaf(__shfl_sync(FULL, xv, k), __ldg(Ws1 + k * F_ + f), hs);
        hs = fmaxf(hs, 0.0f);
        float xs = __ldg(bs2 + f);
        #pragma unroll
        for (int k = 0; k < F_; k++)
            xs = fmaf(__shfl_sync(FULL, hs, k), __ldg(Ws2 + k * F_ + f), xs);
        xs = fmaxf(xs, 0.0f);

        float rowsum = 0.0f, ssum = 0.0f;
        #pragma unroll
        for (int w8 = 0; w8 < 8; w8++) {
            rowsum += s_asum[w8];
            ssum   += sacc[w8][f];
        }
        float inv = 1.0f / fmaxf(rowsum, 1e-12f);
        outX2[(size_t)bi * F_ + f] = fmaf(ssum, inv, xs);
    }
    // bulk stores drain at kernel completion
}

// ---------------------------------------------------------------------------
// Launch. Inputs (metadata order): A, W, x, Wn1, bn1, Wn2, bn2, Ws1, bs1,
// Ws2, bs2. Output: [W (B*N*N*F) | x2 (B*N*F)] as float32.
// ---------------------------------------------------------------------------
extern "C" void kernel_launch(void* const* d_in, const int* in_sizes, int n_in,
                              void* d_out, int out_size) {
    const float* A   = (const float*)d_in[0];
    const float* W   = (const float*)d_in[1];
    const float* x   = (const float*)d_in[2];
    const float* Wn1 = (const float*)d_in[3];
    const float* bn1 = (const float*)d_in[4];
    const float* Wn2 = (const float*)d_in[5];
    const float* bn2 = (const float*)d_in[6];
    const float* Ws1 = (const float*)d_in[7];
    const float* bs1 = (const float*)d_in[8];
    const float* Ws2 = (const float*)d_in[9];
    const float* bs2 = (const float*)d_in[10];

    float* out   = (float*)d_out;
    float* outW  = out;
    float* outX2 = out + (size_t)B_ * N_ * N_ * F_;

    prep_kernel<<<BN_ / 8, 256>>>(x, Wn1, bn1, Wn2, bn2);
    agg_kernel<<<BN_, 256>>>(A, W, x, Ws1, bs1, Ws2, bs2, outW, outX2);
}

// round 10
// speedup vs baseline: 1.1759x; 1.1759x over previous
#include <cuda_runtime.h>
#include <cstdint>

#define B_  8
#define N_  512
#define F_  32
#define BN_ (B_ * N_)

#define STAGE_J     64                       // j's per pipeline stage
#define STAGE_BYTES (STAGE_J * F_ * 4)       // 8192 B
#define NBUF        4                        // SMEM ring buffers
#define NSTAGES     (N_ / STAGE_J)           // 8 stages per row
#define DEPTH       3                        // fills in flight (safe ordering)

// Scratch (allocation-free rule: __device__ globals)
__device__ float g_x1[BN_ * F_];
__device__ float g_inv[BN_];

__device__ __forceinline__ uint32_t smem_u32(const void* p) {
    return (uint32_t)__cvta_generic_to_shared(p);
}

// ---------------------------------------------------------------------------
// Prep kernel (proven R7 version): one warp per (b,n) row.
//  - g_inv[row] = 1 / max(sum_j A[row,j], eps)   (A is 0/1 -> |A| == A)
//  - g_x1  = relu(relu(x@Wn1+bn1)@Wn2+bn2)
//  - outX2 = relu(relu(x@Ws1+bs1)@Ws2+bs2)       (self path; agg adds onto it)
// ---------------------------------------------------------------------------
__global__ __launch_bounds__(256)
void prep_kernel(const float* __restrict__ x, const float* __restrict__ A,
                 const float* __restrict__ Wn1, const float* __restrict__ bn1,
                 const float* __restrict__ Wn2, const float* __restrict__ bn2,
                 const float* __restrict__ Ws1, const float* __restrict__ bs1,
                 const float* __restrict__ Ws2, const float* __restrict__ bs2,
                 float* __restrict__ outX2) {
    const unsigned FULL = 0xffffffffu;
    int row = blockIdx.x * (blockDim.x >> 5) + (threadIdx.x >> 5);
    int f   = threadIdx.x & 31;
    if (row >= BN_) return;

    const float4* A4 = (const float4*)(A + (size_t)row * N_);
    float s = 0.0f;
    #pragma unroll
    for (int k = 0; k < 4; k++) {
        float4 a = A4[f + k * 32];
        s += (a.x + a.y) + (a.z + a.w);
    }
    #pragma unroll
    for (int o = 16; o; o >>= 1) s += __shfl_xor_sync(FULL, s, o);
    if (f == 0) g_inv[row] = 1.0f / fmaxf(s, 1e-12f);

    float xv = x[row * F_ + f];

    float h = bn1[f];
    #pragma unroll
    for (int k = 0; k < F_; k++)
        h = fmaf(__shfl_sync(FULL, xv, k), Wn1[k * F_ + f], h);
    h = fmaxf(h, 0.0f);
    float o1 = bn2[f];
    #pragma unroll
    for (int k = 0; k < F_; k++)
        o1 = fmaf(__shfl_sync(FULL, h, k), Wn2[k * F_ + f], o1);
    g_x1[row * F_ + f] = fmaxf(o1, 0.0f);

    float hs = bs1[f];
    #pragma unroll
    for (int k = 0; k < F_; k++)
        hs = fmaf(__shfl_sync(FULL, xv, k), Ws1[k * F_ + f], hs);
    hs = fmaxf(hs, 0.0f);
    float o2 = bs2[f];
    #pragma unroll
    for (int k = 0; k < F_; k++)
        o2 = fmaf(__shfl_sync(FULL, hs, k), Ws2[k * F_ + f], o2);
    outX2[row * F_ + f] = fmaxf(o2, 0.0f);
}

// ---------------------------------------------------------------------------
// Aggregation + W copy via bulk-async pipeline. One block = one row (bi).
// Proven-safe ordering: consumer wait -> compute -> __syncthreads ->
// copy-out + refill. SINGLE change vs the 79.7us R7 kernel: DEPTH 2 -> 3.
//  refill at stage s targets buf (s+3)&3 = (s-1)&3, consumed at stage s-1
//  (its end-sync precedes stage s); copy-out reads of that buffer (group
//  G_{s-1}) are drained by wait_group.read 1 after committing G_s.
// ---------------------------------------------------------------------------
__global__ __launch_bounds__(256)
void agg_kernel(const float* __restrict__ A, const float* __restrict__ W,
                float* __restrict__ outW, float* __restrict__ outX2) {
    __shared__ __align__(128) float sbuf[NBUF][STAGE_J * F_];   // 32 KB
    __shared__ __align__(8) unsigned long long mbar[NBUF];
    __shared__ float sacc[8][F_];

    const unsigned FULL = 0xffffffffu;
    int bi   = blockIdx.x;            // row (b*N + i)
    int b    = bi >> 9;               // N_ = 512
    int tid  = threadIdx.x;
    int warp = tid >> 5;
    int lane = tid & 31;
    int fq   = lane & 7;
    int jo   = lane >> 3;

    const char* Wrow = (const char*)(W    + (size_t)bi * N_ * F_);
    char*       Orow = (char*)      (outW + (size_t)bi * N_ * F_);
    const float4* x1p  = (const float4*)(g_x1 + (size_t)b * N_ * F_);
    const float*  Arow = A + (size_t)bi * N_;

    uint32_t sbuf_s = smem_u32(&sbuf[0][0]);
    uint32_t mbar_s = smem_u32(&mbar[0]);

    if (tid == 0) {
        #pragma unroll
        for (int i = 0; i < NBUF; i++)
            asm volatile("mbarrier.init.shared::cta.b64 [%0], 1;"
                         :: "r"(mbar_s + i * 8) : "memory");
    }
    __syncthreads();

    // prologue: fill stages 0..DEPTH-1
    if (tid == 0) {
        #pragma unroll
        for (int s = 0; s < DEPTH; s++) {
            uint32_t mb = mbar_s + s * 8;
            asm volatile("mbarrier.arrive.expect_tx.shared::cta.b64 _, [%0], %1;"
                         :: "r"(mb), "r"((uint32_t)STAGE_BYTES) : "memory");
            asm volatile(
                "cp.async.bulk.shared::cluster.global.mbarrier::complete_tx::bytes"
                " [%0], [%1], %2, [%3];"
                :: "r"(sbuf_s + s * STAGE_BYTES),
                   "l"(Wrow + (size_t)s * STAGE_BYTES),
                   "r"((uint32_t)STAGE_BYTES), "r"(mb) : "memory");
        }
    }

    float4 acc = make_float4(0.0f, 0.0f, 0.0f, 0.0f);

    for (int s = 0; s < NSTAGES; s++) {
        int p = s & (NBUF - 1);
        uint32_t mb  = mbar_s + p * 8;
        uint32_t phs = (uint32_t)((s >> 2) & 1);

        // consumer wait (acquire) -- fill for stage s complete
        {
            uint32_t done;
            asm volatile(
                "{ .reg .pred q;\n\t"
                "mbarrier.try_wait.parity.acquire.cta.shared::cta.b64 q, [%1], %2;\n\t"
                "selp.b32 %0, 1, 0, q; }"
                : "=r"(done) : "r"(mb), "r"(phs) : "memory");
            if (!done) {
                asm volatile(
                    "{ .reg .pred q;\n\t"
                    "WL_%=:\n\t"
                    "mbarrier.try_wait.parity.acquire.cta.shared::cta.b64 q, [%0], %1, 0x989680;\n\t"
                    "@q bra.uni WD_%=;\n\t"
                    "bra.uni WL_%=;\n\t"
                    "WD_%=: }"
                    :: "r"(mb), "r"(phs) : "memory");
            }
        }

        uint32_t buf = sbuf_s + p * STAGE_BYTES;

        // compute: warp handles 8 j's of this 64-j stage (2 iters of 4 j)
        #pragma unroll
        for (int k = 0; k < 2; k++) {
            uint32_t a0_, a1_, a2_, a3_;
            asm volatile("ld.shared.v4.b32 {%0,%1,%2,%3}, [%4];"
                         : "=r"(a0_), "=r"(a1_), "=r"(a2_), "=r"(a3_)
                         : "r"(buf + warp * 1024 + k * 512 + lane * 16));
            float4 w4;
            w4.x = __uint_as_float(a0_); w4.y = __uint_as_float(a1_);
            w4.z = __uint_as_float(a2_); w4.w = __uint_as_float(a3_);
            int j = s * STAGE_J + warp * 8 + k * 4 + jo;
            float  a  = __ldg(Arow + j);
            float4 xv = x1p[j * 8 + fq];          // fully coalesced 512B/warp
            acc.x = fmaf(a * w4.x, xv.x, acc.x);
            acc.y = fmaf(a * w4.y, xv.y, acc.y);
            acc.z = fmaf(a * w4.z, xv.z, acc.z);
            acc.w = fmaf(a * w4.w, xv.w, acc.w);
        }

        __syncthreads();   // all warps done reading buf p

        if (tid == 0) {
            // copy-out this stage (reads SMEM asynchronously)
            asm volatile("cp.async.bulk.global.shared::cta.bulk_group [%0], [%1], %2;"
                         :: "l"(Orow + (size_t)s * STAGE_BYTES),
                            "r"(buf), "r"((uint32_t)STAGE_BYTES) : "memory");
            asm volatile("cp.async.bulk.commit_group;" ::: "memory");

            int s2 = s + DEPTH;
            if (s2 < NSTAGES) {
                // refill target buf (s-1)&3: drain its copy-out group G_{s-1}
                // (allow the just-committed G_s to stay pending)
                asm volatile("cp.async.bulk.wait_group.read 1;" ::: "memory");
                int p2 = s2 & (NBUF - 1);
                uint32_t mb2 = mbar_s + p2 * 8;
                asm volatile("mbarrier.arrive.expect_tx.shared::cta.b64 _, [%0], %1;"
                             :: "r"(mb2), "r"((uint32_t)STAGE_BYTES) : "memory");
                asm volatile(
                    "cp.async.bulk.shared::cluster.global.mbarrier::complete_tx::bytes"
                    " [%0], [%1], %2, [%3];"
                    :: "r"(sbuf_s + p2 * STAGE_BYTES),
                       "l"(Wrow + (size_t)s2 * STAGE_BYTES),
                       "r"((uint32_t)STAGE_BYTES), "r"(mb2) : "memory");
            }
        }
    }

    // reduce across the 4 lanes sharing a feature-quad (xor 8, 16)
    #pragma unroll
    for (int o = 8; o <= 16; o <<= 1) {
        acc.x += __shfl_xor_sync(FULL, acc.x, o);
        acc.y += __shfl_xor_sync(FULL, acc.y, o);
        acc.z += __shfl_xor_sync(FULL, acc.z, o);
        acc.w += __shfl_xor_sync(FULL, acc.w, o);
    }
    if (lane < 8) {
        sacc[warp][lane * 4 + 0] = acc.x;
        sacc[warp][lane * 4 + 1] = acc.y;
        sacc[warp][lane * 4 + 2] = acc.z;
        sacc[warp][lane * 4 + 3] = acc.w;
    }
    __syncthreads();

    // block owns the full row: plain read-modify-write (prep stored xs here)
    if (tid < F_) {
        float ssum = 0.0f;
        #pragma unroll
        for (int w8 = 0; w8 < 8; w8++) ssum += sacc[w8][tid];
        float* dst = outX2 + (size_t)bi * F_ + tid;
        *dst = fmaf(ssum, g_inv[bi], *dst);
    }
    // bulk stores drain at kernel completion
}

// ---------------------------------------------------------------------------
// Launch. Inputs (metadata order): A, W, x, Wn1, bn1, Wn2, bn2, Ws1, bs1,
// Ws2, bs2. Output: [W (B*N*N*F) | x2 (B*N*F)] as float32.
// ---------------------------------------------------------------------------
extern "C" void kernel_launch(void* const* d_in, const int* in_sizes, int n_in,
                              void* d_out, int out_size) {
    const float* A   = (const float*)d_in[0];
    const float* W   = (const float*)d_in[1];
    const float* x   = (const float*)d_in[2];
    const float* Wn1 = (const float*)d_in[3];
    const float* bn1 = (const float*)d_in[4];
    const float* Wn2 = (const float*)d_in[5];
    const float* bn2 = (const float*)d_in[6];
    const float* Ws1 = (const float*)d_in[7];
    const float* bs1 = (const float*)d_in[8];
    const float* Ws2 = (const float*)d_in[9];
    const float* bs2 = (const float*)d_in[10];

    float* out   = (float*)d_out;
    float* outW  = out;
    float* outX2 = out + (size_t)B_ * N_ * N_ * F_;

    prep_kernel<<<BN_ / 8, 256>>>(x, A, Wn1, bn1, Wn2, bn2,
                                  Ws1, bs1, Ws2, bs2, outX2);
    agg_kernel<<<BN_, 256>>>(A, W, outW, outX2);
}

// round 11
// speedup vs baseline: 1.1796x; 1.0031x over previous
#include <cuda_runtime.h>
#include <cstdint>

#define B_  8
#define N_  512
#define F_  32
#define BN_ (B_ * N_)

#define STAGE_J     64                       // j's per pipeline stage
#define STAGE_BYTES (STAGE_J * F_ * 4)       // 8192 B
#define NBUF        4                        // SMEM ring buffers
#define NSTAGES     (N_ / STAGE_J)           // 8 stages per row
#define DEPTH       3                        // fills in flight (safe ordering)

// Scratch (allocation-free rule: __device__ globals)
__device__ float g_x1[BN_ * F_];
__device__ float g_inv[BN_];

__device__ __forceinline__ uint32_t smem_u32(const void* p) {
    return (uint32_t)__cvta_generic_to_shared(p);
}

// ---------------------------------------------------------------------------
// Prep kernel (proven R7 version): one warp per (b,n) row.
//  - g_inv[row] = 1 / max(sum_j A[row,j], eps)   (A is 0/1 -> |A| == A)
//  - g_x1  = relu(relu(x@Wn1+bn1)@Wn2+bn2)
//  - outX2 = relu(relu(x@Ws1+bs1)@Ws2+bs2)       (self path; agg adds onto it)
// ---------------------------------------------------------------------------
__global__ __launch_bounds__(256)
void prep_kernel(const float* __restrict__ x, const float* __restrict__ A,
                 const float* __restrict__ Wn1, const float* __restrict__ bn1,
                 const float* __restrict__ Wn2, const float* __restrict__ bn2,
                 const float* __restrict__ Ws1, const float* __restrict__ bs1,
                 const float* __restrict__ Ws2, const float* __restrict__ bs2,
                 float* __restrict__ outX2) {
    const unsigned FULL = 0xffffffffu;
    int row = blockIdx.x * (blockDim.x >> 5) + (threadIdx.x >> 5);
    int f   = threadIdx.x & 31;
    if (row >= BN_) return;

    const float4* A4 = (const float4*)(A + (size_t)row * N_);
    float s = 0.0f;
    #pragma unroll
    for (int k = 0; k < 4; k++) {
        float4 a = A4[f + k * 32];
        s += (a.x + a.y) + (a.z + a.w);
    }
    #pragma unroll
    for (int o = 16; o; o >>= 1) s += __shfl_xor_sync(FULL, s, o);
    if (f == 0) g_inv[row] = 1.0f / fmaxf(s, 1e-12f);

    float xv = x[row * F_ + f];

    float h = bn1[f];
    #pragma unroll
    for (int k = 0; k < F_; k++)
        h = fmaf(__shfl_sync(FULL, xv, k), Wn1[k * F_ + f], h);
    h = fmaxf(h, 0.0f);
    float o1 = bn2[f];
    #pragma unroll
    for (int k = 0; k < F_; k++)
        o1 = fmaf(__shfl_sync(FULL, h, k), Wn2[k * F_ + f], o1);
    g_x1[row * F_ + f] = fmaxf(o1, 0.0f);

    float hs = bs1[f];
    #pragma unroll
    for (int k = 0; k < F_; k++)
        hs = fmaf(__shfl_sync(FULL, xv, k), Ws1[k * F_ + f], hs);
    hs = fmaxf(hs, 0.0f);
    float o2 = bs2[f];
    #pragma unroll
    for (int k = 0; k < F_; k++)
        o2 = fmaf(__shfl_sync(FULL, hs, k), Ws2[k * F_ + f], o2);
    outX2[row * F_ + f] = fmaxf(o2, 0.0f);
}

// ---------------------------------------------------------------------------
// Aggregation + W copy via bulk-async pipeline. One block = one row (bi).
// FROZEN 79.4us loop. Single change: launched with PDL; the prologue
// (mbarrier init + DEPTH TMA fills, which read only W) runs before
// cudaGridDependencySynchronize(), so prep + the inter-kernel gap hide
// under the first-wave TMA fill latency.
// ---------------------------------------------------------------------------
__global__ __launch_bounds__(256)
void agg_kernel(const float* __restrict__ A, const float* __restrict__ W,
                float* __restrict__ outW, float* __restrict__ outX2) {
    __shared__ __align__(128) float sbuf[NBUF][STAGE_J * F_];   // 32 KB
    __shared__ __align__(8) unsigned long long mbar[NBUF];
    __shared__ float sacc[8][F_];

    const unsigned FULL = 0xffffffffu;
    int bi   = blockIdx.x;            // row (b*N + i)
    int b    = bi >> 9;               // N_ = 512
    int tid  = threadIdx.x;
    int warp = tid >> 5;
    int lane = tid & 31;
    int fq   = lane & 7;
    int jo   = lane >> 3;

    const char* Wrow = (const char*)(W    + (size_t)bi * N_ * F_);
    char*       Orow = (char*)      (outW + (size_t)bi * N_ * F_);
    const float4* x1p  = (const float4*)(g_x1 + (size_t)b * N_ * F_);
    const float*  Arow = A + (size_t)bi * N_;

    uint32_t sbuf_s = smem_u32(&sbuf[0][0]);
    uint32_t mbar_s = smem_u32(&mbar[0]);

    if (tid == 0) {
        #pragma unroll
        for (int i = 0; i < NBUF; i++)
            asm volatile("mbarrier.init.shared::cta.b64 [%0], 1;"
                         :: "r"(mbar_s + i * 8) : "memory");
    }
    __syncthreads();

    // prologue: fill stages 0..DEPTH-1 (reads only W -- pre-dependency work)
    if (tid == 0) {
        #pragma unroll
        for (int s = 0; s < DEPTH; s++) {
            uint32_t mb = mbar_s + s * 8;
            asm volatile("mbarrier.arrive.expect_tx.shared::cta.b64 _, [%0], %1;"
                         :: "r"(mb), "r"((uint32_t)STAGE_BYTES) : "memory");
            asm volatile(
                "cp.async.bulk.shared::cluster.global.mbarrier::complete_tx::bytes"
                " [%0], [%1], %2, [%3];"
                :: "r"(sbuf_s + s * STAGE_BYTES),
                   "l"(Wrow + (size_t)s * STAGE_BYTES),
                   "r"((uint32_t)STAGE_BYTES), "r"(mb) : "memory");
        }
    }

    // PDL: wait for prep_kernel's writes (g_x1, g_inv, outX2) to be visible.
    // Everything above touches only W / local SMEM state.
    cudaGridDependencySynchronize();

    float4 acc = make_float4(0.0f, 0.0f, 0.0f, 0.0f);

    for (int s = 0; s < NSTAGES; s++) {
        int p = s & (NBUF - 1);
        uint32_t mb  = mbar_s + p * 8;
        uint32_t phs = (uint32_t)((s >> 2) & 1);

        // consumer wait (acquire) -- fill for stage s complete
        {
            uint32_t done;
            asm volatile(
                "{ .reg .pred q;\n\t"
                "mbarrier.try_wait.parity.acquire.cta.shared::cta.b64 q, [%1], %2;\n\t"
                "selp.b32 %0, 1, 0, q; }"
                : "=r"(done) : "r"(mb), "r"(phs) : "memory");
            if (!done) {
                asm volatile(
                    "{ .reg .pred q;\n\t"
                    "WL_%=:\n\t"
                    "mbarrier.try_wait.parity.acquire.cta.shared::cta.b64 q, [%0], %1, 0x989680;\n\t"
                    "@q bra.uni WD_%=;\n\t"
                    "bra.uni WL_%=;\n\t"
                    "WD_%=: }"
                    :: "r"(mb), "r"(phs) : "memory");
            }
        }

        uint32_t buf = sbuf_s + p * STAGE_BYTES;

        // compute: warp handles 8 j's of this 64-j stage (2 iters of 4 j)
        #pragma unroll
        for (int k = 0; k < 2; k++) {
            uint32_t a0_, a1_, a2_, a3_;
            asm volatile("ld.shared.v4.b32 {%0,%1,%2,%3}, [%4];"
                         : "=r"(a0_), "=r"(a1_), "=r"(a2_), "=r"(a3_)
                         : "r"(buf + warp * 1024 + k * 512 + lane * 16));
            float4 w4;
            w4.x = __uint_as_float(a0_); w4.y = __uint_as_float(a1_);
            w4.z = __uint_as_float(a2_); w4.w = __uint_as_float(a3_);
            int j = s * STAGE_J + warp * 8 + k * 4 + jo;
            float  a  = __ldg(Arow + j);
            float4 xv = x1p[j * 8 + fq];          // fully coalesced 512B/warp
            acc.x = fmaf(a * w4.x, xv.x, acc.x);
            acc.y = fmaf(a * w4.y, xv.y, acc.y);
            acc.z = fmaf(a * w4.z, xv.z, acc.z);
            acc.w = fmaf(a * w4.w, xv.w, acc.w);
        }

        __syncthreads();   // all warps done reading buf p

        if (tid == 0) {
            // copy-out this stage (reads SMEM asynchronously)
            asm volatile("cp.async.bulk.global.shared::cta.bulk_group [%0], [%1], %2;"
                         :: "l"(Orow + (size_t)s * STAGE_BYTES),
                            "r"(buf), "r"((uint32_t)STAGE_BYTES) : "memory");
            asm volatile("cp.async.bulk.commit_group;" ::: "memory");

            int s2 = s + DEPTH;
            if (s2 < NSTAGES) {
                // refill target buf (s-1)&3: drain its copy-out group G_{s-1}
                asm volatile("cp.async.bulk.wait_group.read 1;" ::: "memory");
                int p2 = s2 & (NBUF - 1);
                uint32_t mb2 = mbar_s + p2 * 8;
                asm volatile("mbarrier.arrive.expect_tx.shared::cta.b64 _, [%0], %1;"
                             :: "r"(mb2), "r"((uint32_t)STAGE_BYTES) : "memory");
                asm volatile(
                    "cp.async.bulk.shared::cluster.global.mbarrier::complete_tx::bytes"
                    " [%0], [%1], %2, [%3];"
                    :: "r"(sbuf_s + p2 * STAGE_BYTES),
                       "l"(Wrow + (size_t)s2 * STAGE_BYTES),
                       "r"((uint32_t)STAGE_BYTES), "r"(mb2) : "memory");
            }
        }
    }

    // reduce across the 4 lanes sharing a feature-quad (xor 8, 16)
    #pragma unroll
    for (int o = 8; o <= 16; o <<= 1) {
        acc.x += __shfl_xor_sync(FULL, acc.x, o);
        acc.y += __shfl_xor_sync(FULL, acc.y, o);
        acc.z += __shfl_xor_sync(FULL, acc.z, o);
        acc.w += __shfl_xor_sync(FULL, acc.w, o);
    }
    if (lane < 8) {
        sacc[warp][lane * 4 + 0] = acc.x;
        sacc[warp][lane * 4 + 1] = acc.y;
        sacc[warp][lane * 4 + 2] = acc.z;
        sacc[warp][lane * 4 + 3] = acc.w;
    }
    __syncthreads();

    // block owns the full row: plain read-modify-write (prep stored xs here)
    if (tid < F_) {
        float ssum = 0.0f;
        #pragma unroll
        for (int w8 = 0; w8 < 8; w8++) ssum += sacc[w8][tid];
        float* dst = outX2 + (size_t)bi * F_ + tid;
        *dst = fmaf(ssum, g_inv[bi], *dst);
    }
    // bulk stores drain at kernel completion
}

// ---------------------------------------------------------------------------
// Launch. Inputs (metadata order): A, W, x, Wn1, bn1, Wn2, bn2, Ws1, bs1,
// Ws2, bs2. Output: [W (B*N*N*F) | x2 (B*N*F)] as float32.
// agg launched with PDL (programmatic stream serialization) so its TMA
// prologue overlaps prep_kernel's tail; the grid-dependency sync inside agg
// enforces the g_x1/g_inv/outX2 ordering.
// ---------------------------------------------------------------------------
extern "C" void kernel_launch(void* const* d_in, const int* in_sizes, int n_in,
                              void* d_out, int out_size) {
    const float* A   = (const float*)d_in[0];
    const float* W   = (const float*)d_in[1];
    const float* x   = (const float*)d_in[2];
    const float* Wn1 = (const float*)d_in[3];
    const float* bn1 = (const float*)d_in[4];
    const float* Wn2 = (const float*)d_in[5];
    const float* bn2 = (const float*)d_in[6];
    const float* Ws1 = (const float*)d_in[7];
    const float* bs1 = (const float*)d_in[8];
    const float* Ws2 = (const float*)d_in[9];
    const float* bs2 = (const float*)d_in[10];

    float* out   = (float*)d_out;
    float* outW  = out;
    float* outX2 = out + (size_t)B_ * N_ * N_ * F_;

    prep_kernel<<<BN_ / 8, 256>>>(x, A, Wn1, bn1, Wn2, bn2,
                                  Ws1, bs1, Ws2, bs2, outX2);

    cudaLaunchConfig_t cfg = {};
    cfg.gridDim  = dim3(BN_, 1, 1);
    cfg.blockDim = dim3(256, 1, 1);
    cfg.dynamicSmemBytes = 0;
    cfg.stream = 0;
    cudaLaunchAttribute attr[1];
    attr[0].id = cudaLaunchAttributeProgrammaticStreamSerialization;
    attr[0].val.programmaticStreamSerializationAllowed = 1;
    cfg.attrs = attr;
    cfg.numAttrs = 1;
    cudaLaunchKernelEx(&cfg, agg_kernel, A, W, outW, outX2);
}

// round 12
// speedup vs baseline: 1.1967x; 1.0145x over previous
#include <cuda_runtime.h>
#include <cstdint>

#define B_  8
#define N_  512
#define F_  32
#define BN_ (B_ * N_)

#define STAGE_J     64                       // j's per pipeline stage
#define STAGE_BYTES (STAGE_J * F_ * 4)       // 8192 B
#define NBUF        4                        // SMEM ring buffers
#define NSTAGES     (N_ / STAGE_J)           // 8 stages per row
#define DEPTH       3                        // fills in flight (safe ordering)

// Scratch (allocation-free rule: __device__ globals)
__device__ float g_x1[BN_ * F_];

__device__ __forceinline__ uint32_t smem_u32(const void* p) {
    return (uint32_t)__cvta_generic_to_shared(p);
}

// ---------------------------------------------------------------------------
// Prep kernel (slim): one warp per (b,n) row; reads only x + MLP weights.
//  - g_x1  = relu(relu(x@Wn1+bn1)@Wn2+bn2)
//  - outX2 = relu(relu(x@Ws1+bs1)@Ws2+bs2)   (self path; agg adds onto it)
// A row-sum moved into agg's pre-PDL prologue (A never touched here).
// ---------------------------------------------------------------------------
__global__ __launch_bounds__(256)
void prep_kernel(const float* __restrict__ x,
                 const float* __restrict__ Wn1, const float* __restrict__ bn1,
                 const float* __restrict__ Wn2, const float* __restrict__ bn2,
                 const float* __restrict__ Ws1, const float* __restrict__ bs1,
                 const float* __restrict__ Ws2, const float* __restrict__ bs2,
                 float* __restrict__ outX2) {
    const unsigned FULL = 0xffffffffu;
    int row = blockIdx.x * (blockDim.x >> 5) + (threadIdx.x >> 5);
    int f   = threadIdx.x & 31;
    if (row >= BN_) return;

    float xv = x[row * F_ + f];

    // two independent MLP chains (n / s) -- interleaved for ILP
    float h  = bn1[f];
    float hs = bs1[f];
    #pragma unroll
    for (int k = 0; k < F_; k++) {
        float xk = __shfl_sync(FULL, xv, k);
        h  = fmaf(xk, Wn1[k * F_ + f], h);
        hs = fmaf(xk, Ws1[k * F_ + f], hs);
    }
    h  = fmaxf(h, 0.0f);
    hs = fmaxf(hs, 0.0f);

    float o1 = bn2[f];
    float o2 = bs2[f];
    #pragma unroll
    for (int k = 0; k < F_; k++) {
        o1 = fmaf(__shfl_sync(FULL, h,  k), Wn2[k * F_ + f], o1);
        o2 = fmaf(__shfl_sync(FULL, hs, k), Ws2[k * F_ + f], o2);
    }
    g_x1[row * F_ + f]  = fmaxf(o1, 0.0f);
    outX2[row * F_ + f] = fmaxf(o2, 0.0f);
}

// ---------------------------------------------------------------------------
// Aggregation + W copy via bulk-async pipeline. One block = one row (bi).
// FROZEN 79.4us loop. Prologue (pre-PDL, reads only A/W):
//   mbar init -> DEPTH TMA fills of W -> A row-sum (also warms L1 for the
//   loop's per-j A loads) -> s_inv. Then cudaGridDependencySynchronize.
// ---------------------------------------------------------------------------
__global__ __launch_bounds__(256)
void agg_kernel(const float* __restrict__ A, const float* __restrict__ W,
                float* __restrict__ outW, float* __restrict__ outX2) {
    __shared__ __align__(128) float sbuf[NBUF][STAGE_J * F_];   // 32 KB
    __shared__ __align__(8) unsigned long long mbar[NBUF];
    __shared__ float sacc[8][F_];
    __shared__ float s_ws[8];
    __shared__ float s_inv;

    const unsigned FULL = 0xffffffffu;
    int bi   = blockIdx.x;            // row (b*N + i)
    int b    = bi >> 9;               // N_ = 512
    int tid  = threadIdx.x;
    int warp = tid >> 5;
    int lane = tid & 31;
    int fq   = lane & 7;
    int jo   = lane >> 3;

    const char* Wrow = (const char*)(W    + (size_t)bi * N_ * F_);
    char*       Orow = (char*)      (outW + (size_t)bi * N_ * F_);
    const float4* x1p  = (const float4*)(g_x1 + (size_t)b * N_ * F_);
    const float*  Arow = A + (size_t)bi * N_;

    uint32_t sbuf_s = smem_u32(&sbuf[0][0]);
    uint32_t mbar_s = smem_u32(&mbar[0]);

    if (tid == 0) {
        #pragma unroll
        for (int i = 0; i < NBUF; i++)
            asm volatile("mbarrier.init.shared::cta.b64 [%0], 1;"
                         :: "r"(mbar_s + i * 8) : "memory");
    }
    __syncthreads();

    // prologue A: fill stages 0..DEPTH-1 (reads only W)
    if (tid == 0) {
        #pragma unroll
        for (int s = 0; s < DEPTH; s++) {
            uint32_t mb = mbar_s + s * 8;
            asm volatile("mbarrier.arrive.expect_tx.shared::cta.b64 _, [%0], %1;"
                         :: "r"(mb), "r"((uint32_t)STAGE_BYTES) : "memory");
            asm volatile(
                "cp.async.bulk.shared::cluster.global.mbarrier::complete_tx::bytes"
                " [%0], [%1], %2, [%3];"
                :: "r"(sbuf_s + s * STAGE_BYTES),
                   "l"(Wrow + (size_t)s * STAGE_BYTES),
                   "r"((uint32_t)STAGE_BYTES), "r"(mb) : "memory");
        }
    }

    // prologue B: A row-sum (reads only A; warms L1 for the loop's A loads)
    {
        float as = 0.0f;
        if (tid < 128) {                       // 128 float4 = 512 floats
            float4 av = ((const float4*)Arow)[tid];
            as = (av.x + av.y) + (av.z + av.w);
        }
        #pragma unroll
        for (int o = 16; o; o >>= 1) as += __shfl_xor_sync(FULL, as, o);
        if (lane == 0) s_ws[warp] = as;
        __syncthreads();
        if (tid == 0) {
            float rowsum = s_ws[0] + s_ws[1] + s_ws[2] + s_ws[3];
            s_inv = 1.0f / fmaxf(rowsum, 1e-12f);
        }
    }

    // PDL: wait for prep_kernel's writes (g_x1, outX2) to be visible.
    cudaGridDependencySynchronize();

    float4 acc = make_float4(0.0f, 0.0f, 0.0f, 0.0f);

    for (int s = 0; s < NSTAGES; s++) {
        int p = s & (NBUF - 1);
        uint32_t mb  = mbar_s + p * 8;
        uint32_t phs = (uint32_t)((s >> 2) & 1);

        // consumer wait (acquire) -- fill for stage s complete
        {
            uint32_t done;
            asm volatile(
                "{ .reg .pred q;\n\t"
                "mbarrier.try_wait.parity.acquire.cta.shared::cta.b64 q, [%1], %2;\n\t"
                "selp.b32 %0, 1, 0, q; }"
                : "=r"(done) : "r"(mb), "r"(phs) : "memory");
            if (!done) {
                asm volatile(
                    "{ .reg .pred q;\n\t"
                    "WL_%=:\n\t"
                    "mbarrier.try_wait.parity.acquire.cta.shared::cta.b64 q, [%0], %1, 0x989680;\n\t"
                    "@q bra.uni WD_%=;\n\t"
                    "bra.uni WL_%=;\n\t"
                    "WD_%=: }"
                    :: "r"(mb), "r"(phs) : "memory");
            }
        }

        uint32_t buf = sbuf_s + p * STAGE_BYTES;

        // compute: warp handles 8 j's of this 64-j stage (2 iters of 4 j)
        #pragma unroll
        for (int k = 0; k < 2; k++) {
            uint32_t a0_, a1_, a2_, a3_;
            asm volatile("ld.shared.v4.b32 {%0,%1,%2,%3}, [%4];"
                         : "=r"(a0_), "=r"(a1_), "=r"(a2_), "=r"(a3_)
                         : "r"(buf + warp * 1024 + k * 512 + lane * 16));
            float4 w4;
            w4.x = __uint_as_float(a0_); w4.y = __uint_as_float(a1_);
            w4.z = __uint_as_float(a2_); w4.w = __uint_as_float(a3_);
            int j = s * STAGE_J + warp * 8 + k * 4 + jo;
            float  a  = __ldg(Arow + j);          // L1-hot (prologue B)
            float4 xv = x1p[j * 8 + fq];          // fully coalesced 512B/warp
            acc.x = fmaf(a * w4.x, xv.x, acc.x);
            acc.y = fmaf(a * w4.y, xv.y, acc.y);
            acc.z = fmaf(a * w4.z, xv.z, acc.z);
            acc.w = fmaf(a * w4.w, xv.w, acc.w);
        }

        __syncthreads();   // all warps done reading buf p

        if (tid == 0) {
            // copy-out this stage (reads SMEM asynchronously)
            asm volatile("cp.async.bulk.global.shared::cta.bulk_group [%0], [%1], %2;"
                         :: "l"(Orow + (size_t)s * STAGE_BYTES),
                            "r"(buf), "r"((uint32_t)STAGE_BYTES) : "memory");
            asm volatile("cp.async.bulk.commit_group;" ::: "memory");

            int s2 = s + DEPTH;
            if (s2 < NSTAGES) {
                // refill target buf (s-1)&3: drain its copy-out group G_{s-1}
                asm volatile("cp.async.bulk.wait_group.read 1;" ::: "memory");
                int p2 = s2 & (NBUF - 1);
                uint32_t mb2 = mbar_s + p2 * 8;
                asm volatile("mbarrier.arrive.expect_tx.shared::cta.b64 _, [%0], %1;"
                             :: "r"(mb2), "r"((uint32_t)STAGE_BYTES) : "memory");
                asm volatile(
                    "cp.async.bulk.shared::cluster.global.mbarrier::complete_tx::bytes"
                    " [%0], [%1], %2, [%3];"
                    :: "r"(sbuf_s + p2 * STAGE_BYTES),
                       "l"(Wrow + (size_t)s2 * STAGE_BYTES),
                       "r"((uint32_t)STAGE_BYTES), "r"(mb2) : "memory");
            }
        }
    }

    // reduce across the 4 lanes sharing a feature-quad (xor 8, 16)
    #pragma unroll
    for (int o = 8; o <= 16; o <<= 1) {
        acc.x += __shfl_xor_sync(FULL, acc.x, o);
        acc.y += __shfl_xor_sync(FULL, acc.y, o);
        acc.z += __shfl_xor_sync(FULL, acc.z, o);
        acc.w += __shfl_xor_sync(FULL, acc.w, o);
    }
    if (lane < 8) {
        sacc[warp][lane * 4 + 0] = acc.x;
        sacc[warp][lane * 4 + 1] = acc.y;
        sacc[warp][lane * 4 + 2] = acc.z;
        sacc[warp][lane * 4 + 3] = acc.w;
    }
    __syncthreads();

    // block owns the full row: plain read-modify-write (prep stored xs here)
    if (tid < F_) {
        float ssum = 0.0f;
        #pragma unroll
        for (int w8 = 0; w8 < 8; w8++) ssum += sacc[w8][tid];
        float* dst = outX2 + (size_t)bi * F_ + tid;
        *dst = fmaf(ssum, s_inv, *dst);
    }
    // bulk stores drain at kernel completion
}

// ---------------------------------------------------------------------------
// Launch. Inputs (metadata order): A, W, x, Wn1, bn1, Wn2, bn2, Ws1, bs1,
// Ws2, bs2. Output: [W (B*N*N*F) | x2 (B*N*F)] as float32.
// agg launched with PDL; its lengthened prologue (TMA fills + A row-sum)
// overlaps the slimmed prep (x-only, ~2-3us).
// ---------------------------------------------------------------------------
extern "C" void kernel_launch(void* const* d_in, const int* in_sizes, int n_in,
                              void* d_out, int out_size) {
    const float* A   = (const float*)d_in[0];
    const float* W   = (const float*)d_in[1];
    const float* x   = (const float*)d_in[2];
    const float* Wn1 = (const float*)d_in[3];
    const float* bn1 = (const float*)d_in[4];
    const float* Wn2 = (const float*)d_in[5];
    const float* bn2 = (const float*)d_in[6];
    const float* Ws1 = (const float*)d_in[7];
    const float* bs1 = (const float*)d_in[8];
    const float* Ws2 = (const float*)d_in[9];
    const float* bs2 = (const float*)d_in[10];

    float* out   = (float*)d_out;
    float* outW  = out;
    float* outX2 = out + (size_t)B_ * N_ * N_ * F_;

    prep_kernel<<<BN_ / 8, 256>>>(x, Wn1, bn1, Wn2, bn2,
                                  Ws1, bs1, Ws2, bs2, outX2);

    cudaLaunchConfig_t cfg = {};
    cfg.gridDim  = dim3(BN_, 1, 1);
    cfg.blockDim = dim3(256, 1, 1);
    cfg.dynamicSmemBytes = 0;
    cfg.stream = 0;
    cudaLaunchAttribute attr[1];
    attr[0].id = cudaLaunchAttributeProgrammaticStreamSerialization;
    attr[0].val.programmaticStreamSerializationAllowed = 1;
    cfg.attrs = attr;
    cfg.numAttrs = 1;
    cudaLaunchKernelEx(&cfg, agg_kernel, A, W, outW, outX2);
}